// round 14
// baseline (speedup 1.0000x reference)
#include <cuda_runtime.h>
#include <cuda_fp16.h>
#include <math.h>
#include <float.h>
#include <stdint.h>

#define NMAX 16384
#define KNN 20

// ---------------- scratch (device globals; no allocation allowed) ----------
__device__ float g_Z [NMAX * 1216];
__device__ float g_Y [NMAX * 64];
__device__ float g_Fc[NMAX * 64];
__device__ float g_P [NMAX * 96];
__device__ float g_Z1[NMAX * 256];
__device__ float g_Z2[NMAX * 256];
__device__ float g_Z3[NMAX * 128];
__device__ int   g_idx[NMAX * KNN];
__device__ int   g_idx2[NMAX * KNN];   // probe scratch (R14 timing experiment)
__device__ float g_norm[NMAX];
__device__ __half g_hi[NMAX * 64];
__device__ __half g_lo[NMAX * 64];

// ---------------- helpers ----------------------------------------------------
__device__ __forceinline__ uint32_t smem_to_u32(const void* p) {
    uint32_t a;
    asm("{ .reg .u64 t; cvta.to.shared.u64 t, %1; cvt.u32.u64 %0, t; }"
        : "=r"(a) : "l"(p));
    return a;
}
__device__ __forceinline__ void cp_async16(uint32_t dst, const void* src) {
    asm volatile("cp.async.cg.shared.global [%0], [%1], 16;"
                 :: "r"(dst), "l"(src) : "memory");
}
__device__ __forceinline__ void cp_commit() {
    asm volatile("cp.async.commit_group;" ::: "memory");
}
__device__ __forceinline__ void cp_wait0() {
    asm volatile("cp.async.wait_group 0;" ::: "memory");
}
__device__ __forceinline__ void ldsm_x4(uint32_t& r0, uint32_t& r1,
                                        uint32_t& r2, uint32_t& r3, uint32_t a) {
    asm volatile("ldmatrix.sync.aligned.m8n8.x4.shared.b16 {%0,%1,%2,%3}, [%4];"
                 : "=r"(r0), "=r"(r1), "=r"(r2), "=r"(r3) : "r"(a));
}
__device__ __forceinline__ void mma_f16(float& c0, float& c1, float& c2, float& c3,
                                        uint32_t a0, uint32_t a1, uint32_t a2, uint32_t a3,
                                        uint32_t b0, uint32_t b1) {
    asm volatile("mma.sync.aligned.m16n8k16.row.col.f32.f16.f16.f32 "
                 "{%0,%1,%2,%3}, {%4,%5,%6,%7}, {%8,%9}, {%0,%1,%2,%3};"
                 : "+f"(c0), "+f"(c1), "+f"(c2), "+f"(c3)
                 : "r"(a0), "r"(a1), "r"(a2), "r"(a3), "r"(b0), "r"(b1));
}

// ---------------- packed f32x2 helpers --------------------------------------
typedef unsigned long long ull;
__device__ __forceinline__ void ffma2(ull& acc, ull a, ull b) {
    asm("fma.rn.f32x2 %0, %1, %2, %0;" : "+l"(acc) : "l"(a), "l"(b));
}
__device__ __forceinline__ ull splat2(float x) {
    unsigned int u = __float_as_uint(x);
    ull r;
    asm("mov.b64 %0, {%1, %1};" : "=l"(r) : "r"(u));
    return r;
}
__device__ __forceinline__ void unpack2(ull v, float& lo, float& hi) {
    unsigned int a, b;
    asm("mov.b64 {%0, %1}, %2;" : "=r"(a), "=r"(b) : "l"(v));
    lo = __uint_as_float(a); hi = __uint_as_float(b);
}

// ---------------- fused fp32 -> fp16 hi/lo split + row norms -----------------
template<int DB, int TPR>
__global__ void splitnorm_kernel(const float* __restrict__ F, int ld, int D,
                                 __half* __restrict__ hi,
                                 __half* __restrict__ lo,
                                 float* __restrict__ norms, int n)
{
    int t = blockIdx.x * blockDim.x + threadIdx.x;
    int r = t / TPR, g = t - r * TPR;
    if (r >= n) return;
    int c = g * 2;
    float x0 = (c     < D) ? F[(size_t)r * ld + c]     : 0.f;
    float x1 = (c + 1 < D) ? F[(size_t)r * ld + c + 1] : 0.f;
    __half h0 = __float2half_rn(x0), h1 = __float2half_rn(x1);
    hi[(size_t)r * DB + c]     = h0;
    hi[(size_t)r * DB + c + 1] = h1;
    lo[(size_t)r * DB + c]     = __float2half_rn(x0 - __half2float(h0));
    lo[(size_t)r * DB + c + 1] = __float2half_rn(x1 - __half2float(h1));
    float s = x0 * x0 + x1 * x1;
    #pragma unroll
    for (int o = TPR / 2; o > 0; o >>= 1)
        s += __shfl_xor_sync(0xffffffffu, s, o);
    if (g == 0) norms[r] = s;
}

// ---------------- top-k bubble insert ----------------------------------------
__device__ __forceinline__ void topk_insert(float (&bk)[KNN], int (&bi)[KNN],
                                            float kv, int ci)
{
    float vk = kv; int vi = ci;
    #pragma unroll
    for (int p = 0; p < KNN; ++p) {
        bool sw = vk < bk[p];
        float tf = bk[p]; int ti = bi[p];
        if (sw) { bk[p] = vk; bi[p] = vi; vk = tf; vi = ti; }
    }
}

// ---------------- mma.sync kNN top-20 (R10 structure, fp16 split) ------------
template<int DB>   // fp16 K per term: 16 (D=9) or 64
__global__ __launch_bounds__(256, 1)
void knn_mma_kernel(const __half* __restrict__ Fhi,
                    const __half* __restrict__ Flo,
                    const float* __restrict__ norms,
                    int* __restrict__ out_idx, int n)
{
    constexpr int NSTEP = DB / 16;
    constexpr int CHB = DB / 8;
    constexpr int SQH = DB + 8;
    constexpr int QB  = 128 * SQH * 2;
    constexpr int OFF_QHI = 1024;
    constexpr int OFF_QLO = OFF_QHI + QB;
    constexpr int OFF_C   = OFF_QLO + QB;
    constexpr int OFF_S   = OFF_C + 4 * QB;

    extern __shared__ char smem[];
    const uint32_t sb = smem_to_u32(smem);
    float* sN = (float*)smem;
    float* S  = (float*)(smem + OFF_S);

    const int tid = threadIdx.x;
    const int warp = tid >> 5, lane = tid & 31;
    const int q0 = blockIdx.x * 128;

    auto load_tile = [&](uint32_t dstoff, const __half* src) {
        #pragma unroll
        for (int e = tid; e < 128 * CHB; e += 256) {
            int r = e / CHB, c = e - r * CHB;
            cp_async16(sb + dstoff + (uint32_t)(r * SQH + c * 8) * 2,
                       src + (size_t)r * DB + c * 8);
        }
    };

    load_tile(OFF_QHI, Fhi + (size_t)q0 * DB);
    load_tile(OFF_QLO, Flo + (size_t)q0 * DB);
    load_tile(OFF_C,      Fhi);
    load_tile(OFF_C + QB, Flo);
    if (tid < 32) cp_async16(sb + tid * 16, norms + tid * 4);
    cp_commit();
    cp_wait0();
    __syncthreads();

    const int m0 = warp * 16;
    const uint32_t aOff = (uint32_t)(((m0 + (lane & 15)) * SQH + (lane >> 4) * 8) * 2);
    const uint32_t aHi = sb + OFF_QHI + aOff;
    const uint32_t aLo = sb + OFF_QLO + aOff;
    const uint32_t bOff = (uint32_t)((((lane & 7) + ((lane >> 4) << 3)) * SQH
                                      + ((lane >> 3) & 1) * 8) * 2);

    float best[KNN]; int bidx[KNN];
    #pragma unroll
    for (int k = 0; k < KNN; k++) { best[k] = 3.0e38f; bidx[k] = 0; }
    float worst = 3.0e38f;

    const int selq = tid & 127, selh = tid >> 7;
    const int T = n >> 7;

    for (int t = 0; t < T; t++) {
        const int cur = t & 1, nb = (t + 1) & 1;
        if (t + 1 < T) {
            int row0 = (t + 1) << 7;
            load_tile(OFF_C + nb * 2 * QB,      Fhi + (size_t)row0 * DB);
            load_tile(OFF_C + nb * 2 * QB + QB, Flo + (size_t)row0 * DB);
            if (tid < 32) cp_async16(sb + nb * 512 + tid * 16, norms + row0 + tid * 4);
        }
        cp_commit();

        float acc[16][4];
        #pragma unroll
        for (int f = 0; f < 16; f++)
            #pragma unroll
            for (int j = 0; j < 4; j++) acc[f][j] = 0.f;

        const uint32_t cHi = sb + OFF_C + (uint32_t)(cur * 2 * QB) + bOff;
        const uint32_t cLo = cHi + QB;

        #pragma unroll
        for (int term = 0; term < 3; term++) {
            uint32_t aBase = (term == 2) ? aLo : aHi;
            uint32_t bBase = (term == 1) ? cLo : cHi;
            #pragma unroll
            for (int k = 0; k < NSTEP; k++) {
                uint32_t a0, a1, a2, a3;
                ldsm_x4(a0, a1, a2, a3, aBase + k * 32);
                #pragma unroll
                for (int f = 0; f < 8; f++) {
                    uint32_t b0, b1, b2, b3;
                    ldsm_x4(b0, b1, b2, b3,
                            bBase + k * 32 + (uint32_t)(f * 16 * SQH * 2));
                    mma_f16(acc[2*f][0], acc[2*f][1], acc[2*f][2], acc[2*f][3],
                            a0, a1, a2, a3, b0, b1);
                    mma_f16(acc[2*f+1][0], acc[2*f+1][1], acc[2*f+1][2], acc[2*f+1][3],
                            a0, a1, a2, a3, b2, b3);
                }
            }
        }

        {
            int r0 = m0 + (lane >> 2);
            int cc = (lane & 3) * 2;
            #pragma unroll
            for (int f = 0; f < 16; f++) {
                *(float2*)&S[r0 * 130 + f * 8 + cc] =
                    make_float2(acc[f][0], acc[f][1]);
                *(float2*)&S[(r0 + 8) * 130 + f * 8 + cc] =
                    make_float2(acc[f][2], acc[f][3]);
            }
        }
        __syncthreads();

        {
            const float* srow = S + selq * 130 + selh * 64;
            const float* snp  = sN + cur * 128 + selh * 64;
            int cbaseg = (t << 7) + selh * 64;
            #pragma unroll 4
            for (int j = 0; j < 32; j++) {
                float2 dp = *(const float2*)(srow + 2 * j);
                float2 sn = *(const float2*)(snp + 2 * j);
                float k0 = __fmaf_rn(-2.f, dp.x, sn.x);
                float k1 = __fmaf_rn(-2.f, dp.y, sn.y);
                if (k0 < worst) {
                    topk_insert(best, bidx, k0, cbaseg + 2 * j);
                    worst = best[KNN - 1];
                }
                if (k1 < worst) {
                    topk_insert(best, bidx, k1, cbaseg + 2 * j + 1);
                    worst = best[KNN - 1];
                }
            }
        }
        cp_wait0();
        __syncthreads();
    }

    // ---- merge the two half-lists per query (exact (key,idx) order) ----
    float* keyBuf = S;
    int*   idxBuf = (int*)(S + 128 * 40);
    #pragma unroll
    for (int p = 0; p < KNN; p++) {
        keyBuf[selq * 40 + selh * 20 + p] = best[p];
        idxBuf[selq * 40 + selh * 20 + p] = bidx[p];
    }
    __syncthreads();
    if (selh == 0) {
        const float* ka = keyBuf + selq * 40;
        const float* kb = ka + 20;
        const int*   ia = idxBuf + selq * 40;
        const int*   ib = ia + 20;
        int i = 0, j = 0;
        int* outp = out_idx + (size_t)(q0 + selq) * KNN;
        #pragma unroll
        for (int o = 0; o < KNN; o++) {
            float fa = ka[i], fb = kb[j];
            int va = ia[i], vb = ib[j];
            bool takeA = (fa < fb) || (fa == fb && va < vb);
            outp[o] = takeA ? va : vb;
            if (takeA) i++; else j++;
        }
    }
}

// ---------------- fp32 tiled linear (FFMA2 + global prefetch) ---------------
__global__ __launch_bounds__(256)
void linear_kernel(const float* __restrict__ A, int lda,
                   const float* __restrict__ W,
                   const float* __restrict__ bias,
                   float* __restrict__ C, int ldc,
                   int n, int kin, int kout, int relu)
{
    const int BK = 16;
    __shared__ __align__(16) float As[2][BK][64];
    __shared__ __align__(16) float Bs[2][BK][64];

    int bm = blockIdx.y * 64, bn = blockIdx.x * 64;
    int tid = threadIdx.x;
    int tx = tid & 15, ty = tid >> 4;

    ull acc[4][2];
    #pragma unroll
    for (int i = 0; i < 4; i++) { acc[i][0] = 0ULL; acc[i][1] = 0ULL; }

    float ra[4], rb[4];
    #pragma unroll
    for (int i = 0; i < 4; i++) {
        int l = tid + i * 256;
        { int k = l & 15, m = l >> 4; int gm = bm + m;
          ra[i] = (gm < n && k < kin) ? A[(size_t)gm * lda + k] : 0.f; }
        { int c = l & 63, k = l >> 6; int gc = bn + c;
          rb[i] = (k < kin && gc < kout) ? W[(size_t)k * kout + gc] : 0.f; }
    }

    int nk = (kin + BK - 1) / BK;
    for (int kt = 0; kt < nk; kt++) {
        int cur = kt & 1;
        #pragma unroll
        for (int i = 0; i < 4; i++) {
            int l = tid + i * 256;
            { int k = l & 15, m = l >> 4; As[cur][k][m] = ra[i]; }
            { int c = l & 63, k = l >> 6; Bs[cur][k][c] = rb[i]; }
        }
        __syncthreads();
        if (kt + 1 < nk) {
            int k0 = (kt + 1) * BK;
            #pragma unroll
            for (int i = 0; i < 4; i++) {
                int l = tid + i * 256;
                { int k = l & 15, m = l >> 4; int gm = bm + m, gk = k0 + k;
                  ra[i] = (gm < n && gk < kin) ? A[(size_t)gm * lda + gk] : 0.f; }
                { int c = l & 63, k = l >> 6; int gk = k0 + k, gc = bn + c;
                  rb[i] = (gk < kin && gc < kout) ? W[(size_t)gk * kout + gc] : 0.f; }
            }
        }
        #pragma unroll
        for (int k = 0; k < BK; k++) {
            float4 a4 = ((const float4*)As[cur][k])[ty];
            const ull* br = (const ull*)Bs[cur][k];
            ull b0 = br[tx * 2], b1 = br[tx * 2 + 1];
            ull s0 = splat2(a4.x), s1 = splat2(a4.y);
            ull s2 = splat2(a4.z), s3 = splat2(a4.w);
            ffma2(acc[0][0], s0, b0); ffma2(acc[0][1], s0, b1);
            ffma2(acc[1][0], s1, b0); ffma2(acc[1][1], s1, b1);
            ffma2(acc[2][0], s2, b0); ffma2(acc[2][1], s2, b1);
            ffma2(acc[3][0], s3, b0); ffma2(acc[3][1], s3, b1);
        }
        __syncthreads();
    }

    #pragma unroll
    for (int i = 0; i < 4; i++) {
        int m = bm + ty * 4 + i;
        if (m >= n) continue;
        #pragma unroll
        for (int j = 0; j < 2; j++) {
            float lo, hi;
            unpack2(acc[i][j], lo, hi);
            int c0 = bn + tx * 4 + 2 * j;
            if (c0 < kout) {
                float v = lo + bias[c0];
                if (relu) v = fmaxf(v, 0.f);
                C[(size_t)m * ldc + c0] = v;
            }
            if (c0 + 1 < kout) {
                float v = hi + bias[c0 + 1];
                if (relu) v = fmaxf(v, 0.f);
                C[(size_t)m * ldc + c0 + 1] = v;
            }
        }
    }
}

// ---------------- gather + max over KNN neighbors ---------------------------
__global__ void gathermax_kernel(const float* __restrict__ Y,
                                 const int* __restrict__ idx,
                                 float* __restrict__ out, int ldo,
                                 float* __restrict__ out2, int n)
{
    int i = blockIdx.x;
    if (i >= n) return;
    int d = threadIdx.x; // 64 threads
    const int* ip = idx + (size_t)i * KNN;
    float m = -FLT_MAX;
    #pragma unroll
    for (int k = 0; k < KNN; k++) {
        int j = ip[k];
        m = fmaxf(m, Y[(size_t)j * 64 + d]);
    }
    out[(size_t)i * ldo + d] = m;
    if (out2) out2[(size_t)i * 64 + d] = m;
}

// ---------------- MaxPool1d(2) over first 192 cols of Z ---------------------
__global__ void maxpool_kernel(const float* __restrict__ Z,
                               float* __restrict__ P, int n)
{
    int t = blockIdx.x * blockDim.x + threadIdx.x;
    if (t >= n * 96) return;
    int i = t / 96, j = t - i * 96;
    const float* r = Z + (size_t)i * 1216 + 2 * j;
    P[t] = fmaxf(r[0], r[1]);
}

// -----------------------------------------------------------------------------
extern "C" void kernel_launch(void* const* d_in, const int* in_sizes, int n_in,
                              void* d_out, int out_size)
{
    const float* X   = (const float*)d_in[0];
    const float* w1  = (const float*)d_in[1];
    const float* b1  = (const float*)d_in[2];
    const float* w2  = (const float*)d_in[3];
    const float* b2  = (const float*)d_in[4];
    const float* w3  = (const float*)d_in[5];
    const float* b3  = (const float*)d_in[6];
    const float* wc1 = (const float*)d_in[7];
    const float* bc1 = (const float*)d_in[8];
    const float* wc2 = (const float*)d_in[9];
    const float* bc2 = (const float*)d_in[10];
    const float* wc3 = (const float*)d_in[11];
    const float* bc3 = (const float*)d_in[12];
    const float* wc4 = (const float*)d_in[13];
    const float* bc4 = (const float*)d_in[14];
    float* out = (float*)d_out;

    int n = in_sizes[0] / 9;
    if (n > NMAX) n = NMAX;

    float *Z, *Y, *Fc, *P, *Z1, *Z2, *Z3, *nrm;
    int *idx, *idx2;
    __half *hi, *lo;
    cudaGetSymbolAddress((void**)&Z,    g_Z);
    cudaGetSymbolAddress((void**)&Y,    g_Y);
    cudaGetSymbolAddress((void**)&Fc,   g_Fc);
    cudaGetSymbolAddress((void**)&P,    g_P);
    cudaGetSymbolAddress((void**)&Z1,   g_Z1);
    cudaGetSymbolAddress((void**)&Z2,   g_Z2);
    cudaGetSymbolAddress((void**)&Z3,   g_Z3);
    cudaGetSymbolAddress((void**)&nrm,  g_norm);
    cudaGetSymbolAddress((void**)&idx,  g_idx);
    cudaGetSymbolAddress((void**)&idx2, g_idx2);
    cudaGetSymbolAddress((void**)&hi,   g_hi);
    cudaGetSymbolAddress((void**)&lo,   g_lo);

    int knnB = n / 128;

    const int SM16 = 1024 + 6 * (128 * 24 * 2) + 128 * 130 * 4;  // 104448
    const int SM64 = 1024 + 6 * (128 * 72 * 2) + 128 * 130 * 4;  // 178176
    cudaFuncSetAttribute(knn_mma_kernel<16>,
                         cudaFuncAttributeMaxDynamicSharedMemorySize, SM16);
    cudaFuncSetAttribute(knn_mma_kernel<64>,
                         cudaFuncAttributeMaxDynamicSharedMemorySize, SM64);

    auto lin = [&](const float* A, int lda, const float* W, const float* bias,
                   float* C, int ldc, int kin, int kout, int relu) {
        dim3 grid((kout + 63) / 64, (n + 63) / 64);
        linear_kernel<<<grid, 256>>>(A, lda, W, bias, C, ldc, n, kin, kout, relu);
    };

    // ---- Block 1: knn(X, D=9); Y1 = X@w1+b1; X1 = max-gather
    lin(X, 9, w1, b1, Y, 64, 9, 64, 0);
    splitnorm_kernel<16, 8><<<(n * 8 + 255) / 256, 256>>>(X, 9, 9, hi, lo, nrm, n);
    knn_mma_kernel<16><<<knnB, 256, SM16>>>(hi, lo, nrm, idx, n);
    gathermax_kernel<<<n, 64>>>(Y, idx, Z + 0, 1216, Fc, n);

    // ---- Block 2: knn(X1, D=64); Y2 = X1@w2+b2
    splitnorm_kernel<64, 32><<<(n * 32 + 255) / 256, 256>>>(Fc, 64, 64, hi, lo, nrm, n);
    lin(Fc, 64, w2, b2, Y, 64, 64, 64, 0);
    knn_mma_kernel<64><<<knnB, 256, SM64>>>(hi, lo, nrm, idx, n);
    // ======= R14 TIMING PROBE: two duplicate knn64 launches into scratch ====
    // dur delta vs R10 (4314 us) / 2 == true wall cost of one knn64 launch.
    knn_mma_kernel<64><<<knnB, 256, SM64>>>(hi, lo, nrm, idx2, n);
    knn_mma_kernel<64><<<knnB, 256, SM64>>>(hi, lo, nrm, idx2, n);
    // ========================================================================
    gathermax_kernel<<<n, 64>>>(Y, idx, Z + 64, 1216, Fc, n);

    // ---- Block 3: knn(X2, D=64); Y3 = X2@w2+b2
    splitnorm_kernel<64, 32><<<(n * 32 + 255) / 256, 256>>>(Fc, 64, 64, hi, lo, nrm, n);
    knn_mma_kernel<64><<<knnB, 256, SM64>>>(hi, lo, nrm, idx, n);
    lin(Fc, 64, w2, b2, Y, 64, 64, 64, 0);
    gathermax_kernel<<<n, 64>>>(Y, idx, Z + 128, 1216, (float*)0, n);

    // ---- Head: P = maxpool2(Z[:,0:192]); H = P@w3+b3 -> Z[:,192:1216]
    maxpool_kernel<<<(n * 96 + 255) / 256, 256>>>(Z, P, n);
    lin(P, 96, w3, b3, Z + 192, 1216, 96, 1024, 0);

    // ---- Classifier MLP
    lin(Z,  1216, wc1, bc1, Z1, 256, 1216, 256, 1);
    lin(Z1, 256,  wc2, bc2, Z2, 256, 256,  256, 1);
    lin(Z2, 256,  wc3, bc3, Z3, 128, 256,  128, 1);
    lin(Z3, 128,  wc4, bc4, out, 3, 128,   3,  0);
}

// round 15
// speedup vs baseline: 1.6587x; 1.6587x over previous
#include <cuda_runtime.h>
#include <cuda_fp16.h>
#include <math.h>
#include <float.h>
#include <stdint.h>

#define NMAX 16384
#define KNN 20

// ---------------- scratch (device globals; no allocation allowed) ----------
__device__ float g_Z [NMAX * 1216];
__device__ float g_Y [NMAX * 64];
__device__ float g_Fc[NMAX * 64];
__device__ float g_P [NMAX * 96];
__device__ float g_Z1[NMAX * 256];
__device__ float g_Z2[NMAX * 256];
__device__ float g_Z3[NMAX * 128];
__device__ int   g_idx[NMAX * KNN];
__device__ float g_norm[NMAX];
__device__ __half g_hi[NMAX * 64];
__device__ __half g_lo[NMAX * 64];

// ---------------- helpers ----------------------------------------------------
__device__ __forceinline__ uint32_t smem_to_u32(const void* p) {
    uint32_t a;
    asm("{ .reg .u64 t; cvta.to.shared.u64 t, %1; cvt.u32.u64 %0, t; }"
        : "=r"(a) : "l"(p));
    return a;
}
__device__ __forceinline__ void cp_async16(uint32_t dst, const void* src) {
    asm volatile("cp.async.cg.shared.global [%0], [%1], 16;"
                 :: "r"(dst), "l"(src) : "memory");
}
__device__ __forceinline__ void cp_commit() {
    asm volatile("cp.async.commit_group;" ::: "memory");
}
__device__ __forceinline__ void cp_wait0() {
    asm volatile("cp.async.wait_group 0;" ::: "memory");
}
__device__ __forceinline__ void ldsm_x4(uint32_t& r0, uint32_t& r1,
                                        uint32_t& r2, uint32_t& r3, uint32_t a) {
    asm volatile("ldmatrix.sync.aligned.m8n8.x4.shared.b16 {%0,%1,%2,%3}, [%4];"
                 : "=r"(r0), "=r"(r1), "=r"(r2), "=r"(r3) : "r"(a));
}
__device__ __forceinline__ void mma_f16(float& c0, float& c1, float& c2, float& c3,
                                        uint32_t a0, uint32_t a1, uint32_t a2, uint32_t a3,
                                        uint32_t b0, uint32_t b1) {
    asm volatile("mma.sync.aligned.m16n8k16.row.col.f32.f16.f16.f32 "
                 "{%0,%1,%2,%3}, {%4,%5,%6,%7}, {%8,%9}, {%0,%1,%2,%3};"
                 : "+f"(c0), "+f"(c1), "+f"(c2), "+f"(c3)
                 : "r"(a0), "r"(a1), "r"(a2), "r"(a3), "r"(b0), "r"(b1));
}

// ---------------- packed f32x2 helpers --------------------------------------
typedef unsigned long long ull;
__device__ __forceinline__ void ffma2(ull& acc, ull a, ull b) {
    asm("fma.rn.f32x2 %0, %1, %2, %0;" : "+l"(acc) : "l"(a), "l"(b));
}
__device__ __forceinline__ ull splat2(float x) {
    unsigned int u = __float_as_uint(x);
    ull r;
    asm("mov.b64 %0, {%1, %1};" : "=l"(r) : "r"(u));
    return r;
}
__device__ __forceinline__ void unpack2(ull v, float& lo, float& hi) {
    unsigned int a, b;
    asm("mov.b64 {%0, %1}, %2;" : "=r"(a), "=r"(b) : "l"(v));
    lo = __uint_as_float(a); hi = __uint_as_float(b);
}

// ---------------- fused fp32 -> fp16 hi/lo split + row norms -----------------
template<int DB, int TPR>
__global__ void splitnorm_kernel(const float* __restrict__ F, int ld, int D,
                                 __half* __restrict__ hi,
                                 __half* __restrict__ lo,
                                 float* __restrict__ norms, int n)
{
    int t = blockIdx.x * blockDim.x + threadIdx.x;
    int r = t / TPR, g = t - r * TPR;
    if (r >= n) return;
    int c = g * 2;
    float x0 = (c     < D) ? F[(size_t)r * ld + c]     : 0.f;
    float x1 = (c + 1 < D) ? F[(size_t)r * ld + c + 1] : 0.f;
    __half h0 = __float2half_rn(x0), h1 = __float2half_rn(x1);
    hi[(size_t)r * DB + c]     = h0;
    hi[(size_t)r * DB + c + 1] = h1;
    lo[(size_t)r * DB + c]     = __float2half_rn(x0 - __half2float(h0));
    lo[(size_t)r * DB + c + 1] = __float2half_rn(x1 - __half2float(h1));
    float s = x0 * x0 + x1 * x1;
    #pragma unroll
    for (int o = TPR / 2; o > 0; o >>= 1)
        s += __shfl_xor_sync(0xffffffffu, s, o);
    if (g == 0) norms[r] = s;
}

// ---------------- top-k bubble insert ----------------------------------------
__device__ __forceinline__ void topk_insert(float (&bk)[KNN], int (&bi)[KNN],
                                            float kv, int ci)
{
    float vk = kv; int vi = ci;
    #pragma unroll
    for (int p = 0; p < KNN; ++p) {
        bool sw = vk < bk[p];
        float tf = bk[p]; int ti = bi[p];
        if (sw) { bk[p] = vk; bi[p] = vi; vk = tf; vi = ti; }
    }
}

// ---------------- mma.sync kNN top-20 (R10 structure, fp16 split) ------------
template<int DB>   // fp16 K per term: 16 (D=9) or 64
__global__ __launch_bounds__(256, 1)
void knn_mma_kernel(const __half* __restrict__ Fhi,
                    const __half* __restrict__ Flo,
                    const float* __restrict__ norms,
                    int* __restrict__ out_idx, int n)
{
    constexpr int NSTEP = DB / 16;
    constexpr int CHB = DB / 8;
    constexpr int SQH = DB + 8;
    constexpr int QB  = 128 * SQH * 2;
    constexpr int OFF_QHI = 1024;
    constexpr int OFF_QLO = OFF_QHI + QB;
    constexpr int OFF_C   = OFF_QLO + QB;
    constexpr int OFF_S   = OFF_C + 4 * QB;

    extern __shared__ char smem[];
    const uint32_t sb = smem_to_u32(smem);
    float* sN = (float*)smem;
    float* S  = (float*)(smem + OFF_S);

    const int tid = threadIdx.x;
    const int warp = tid >> 5, lane = tid & 31;
    const int q0 = blockIdx.x * 128;

    auto load_tile = [&](uint32_t dstoff, const __half* src) {
        #pragma unroll
        for (int e = tid; e < 128 * CHB; e += 256) {
            int r = e / CHB, c = e - r * CHB;
            cp_async16(sb + dstoff + (uint32_t)(r * SQH + c * 8) * 2,
                       src + (size_t)r * DB + c * 8);
        }
    };

    load_tile(OFF_QHI, Fhi + (size_t)q0 * DB);
    load_tile(OFF_QLO, Flo + (size_t)q0 * DB);
    load_tile(OFF_C,      Fhi);
    load_tile(OFF_C + QB, Flo);
    if (tid < 32) cp_async16(sb + tid * 16, norms + tid * 4);
    cp_commit();
    cp_wait0();
    __syncthreads();

    const int m0 = warp * 16;
    const uint32_t aOff = (uint32_t)(((m0 + (lane & 15)) * SQH + (lane >> 4) * 8) * 2);
    const uint32_t aHi = sb + OFF_QHI + aOff;
    const uint32_t aLo = sb + OFF_QLO + aOff;
    const uint32_t bOff = (uint32_t)((((lane & 7) + ((lane >> 4) << 3)) * SQH
                                      + ((lane >> 3) & 1) * 8) * 2);

    float best[KNN]; int bidx[KNN];
    #pragma unroll
    for (int k = 0; k < KNN; k++) { best[k] = 3.0e38f; bidx[k] = 0; }
    float worst = 3.0e38f;

    const int selq = tid & 127, selh = tid >> 7;
    const int T = n >> 7;

    for (int t = 0; t < T; t++) {
        const int cur = t & 1, nb = (t + 1) & 1;
        if (t + 1 < T) {
            int row0 = (t + 1) << 7;
            load_tile(OFF_C + nb * 2 * QB,      Fhi + (size_t)row0 * DB);
            load_tile(OFF_C + nb * 2 * QB + QB, Flo + (size_t)row0 * DB);
            if (tid < 32) cp_async16(sb + nb * 512 + tid * 16, norms + row0 + tid * 4);
        }
        cp_commit();

        float acc[16][4];
        #pragma unroll
        for (int f = 0; f < 16; f++)
            #pragma unroll
            for (int j = 0; j < 4; j++) acc[f][j] = 0.f;

        const uint32_t cHi = sb + OFF_C + (uint32_t)(cur * 2 * QB) + bOff;
        const uint32_t cLo = cHi + QB;

        #pragma unroll
        for (int term = 0; term < 3; term++) {
            uint32_t aBase = (term == 2) ? aLo : aHi;
            uint32_t bBase = (term == 1) ? cLo : cHi;
            #pragma unroll
            for (int k = 0; k < NSTEP; k++) {
                uint32_t a0, a1, a2, a3;
                ldsm_x4(a0, a1, a2, a3, aBase + k * 32);
                #pragma unroll
                for (int f = 0; f < 8; f++) {
                    uint32_t b0, b1, b2, b3;
                    ldsm_x4(b0, b1, b2, b3,
                            bBase + k * 32 + (uint32_t)(f * 16 * SQH * 2));
                    mma_f16(acc[2*f][0], acc[2*f][1], acc[2*f][2], acc[2*f][3],
                            a0, a1, a2, a3, b0, b1);
                    mma_f16(acc[2*f+1][0], acc[2*f+1][1], acc[2*f+1][2], acc[2*f+1][3],
                            a0, a1, a2, a3, b2, b3);
                }
            }
        }

        {
            int r0 = m0 + (lane >> 2);
            int cc = (lane & 3) * 2;
            #pragma unroll
            for (int f = 0; f < 16; f++) {
                *(float2*)&S[r0 * 130 + f * 8 + cc] =
                    make_float2(acc[f][0], acc[f][1]);
                *(float2*)&S[(r0 + 8) * 130 + f * 8 + cc] =
                    make_float2(acc[f][2], acc[f][3]);
            }
        }
        __syncthreads();

        {
            const float* srow = S + selq * 130 + selh * 64;
            const float* snp  = sN + cur * 128 + selh * 64;
            int cbaseg = (t << 7) + selh * 64;
            #pragma unroll 4
            for (int j = 0; j < 32; j++) {
                float2 dp = *(const float2*)(srow + 2 * j);
                float2 sn = *(const float2*)(snp + 2 * j);
                float k0 = __fmaf_rn(-2.f, dp.x, sn.x);
                float k1 = __fmaf_rn(-2.f, dp.y, sn.y);
                if (k0 < worst) {
                    topk_insert(best, bidx, k0, cbaseg + 2 * j);
                    worst = best[KNN - 1];
                }
                if (k1 < worst) {
                    topk_insert(best, bidx, k1, cbaseg + 2 * j + 1);
                    worst = best[KNN - 1];
                }
            }
        }
        cp_wait0();
        __syncthreads();
    }

    // ---- merge the two half-lists per query (exact (key,idx) order) ----
    float* keyBuf = S;
    int*   idxBuf = (int*)(S + 128 * 40);
    #pragma unroll
    for (int p = 0; p < KNN; p++) {
        keyBuf[selq * 40 + selh * 20 + p] = best[p];
        idxBuf[selq * 40 + selh * 20 + p] = bidx[p];
    }
    __syncthreads();
    if (selh == 0) {
        const float* ka = keyBuf + selq * 40;
        const float* kb = ka + 20;
        const int*   ia = idxBuf + selq * 40;
        const int*   ib = ia + 20;
        int i = 0, j = 0;
        int* outp = out_idx + (size_t)(q0 + selq) * KNN;
        #pragma unroll
        for (int o = 0; o < KNN; o++) {
            float fa = ka[i], fb = kb[j];
            int va = ia[i], vb = ib[j];
            bool takeA = (fa < fb) || (fa == fb && va < vb);
            outp[o] = takeA ? va : vb;
            if (takeA) i++; else j++;
        }
    }
}

// ---------------- fp32 tiled linear v2: 128x64 tile, 8x4/thread -------------
__global__ __launch_bounds__(256)
void linear_kernel(const float* __restrict__ A, int lda,
                   const float* __restrict__ W,
                   const float* __restrict__ bias,
                   float* __restrict__ C, int ldc,
                   int n, int kin, int kout, int relu)
{
    const int BK = 16;
    __shared__ __align__(16) float As[2][BK][132];   // padded: kills STS conflicts
    __shared__ __align__(16) float Bs[2][BK][64];

    int bm = blockIdx.y * 128, bn = blockIdx.x * 64;
    int tid = threadIdx.x;
    int tx = tid & 15, ty = tid >> 4;   // 16 x 16 thread grid

    ull acc[8][2];
    #pragma unroll
    for (int i = 0; i < 8; i++) { acc[i][0] = 0ULL; acc[i][1] = 0ULL; }

    // register prefetch buffers: 8 A elems + 4 W elems per thread per k-tile
    float ra[8], rb[4];
    #pragma unroll
    for (int i = 0; i < 8; i++) {
        int l = tid + i * 256;
        int k = l & 15, m = l >> 4;     // m 0..127
        int gm = bm + m;
        ra[i] = (gm < n && k < kin) ? A[(size_t)gm * lda + k] : 0.f;
    }
    #pragma unroll
    for (int i = 0; i < 4; i++) {
        int l = tid + i * 256;
        int c = l & 63, k = l >> 6;
        int gc = bn + c;
        rb[i] = (k < kin && gc < kout) ? W[(size_t)k * kout + gc] : 0.f;
    }

    int nk = (kin + BK - 1) / BK;
    for (int kt = 0; kt < nk; kt++) {
        int cur = kt & 1;
        #pragma unroll
        for (int i = 0; i < 8; i++) {
            int l = tid + i * 256;
            int k = l & 15, m = l >> 4;
            As[cur][k][m] = ra[i];
        }
        #pragma unroll
        for (int i = 0; i < 4; i++) {
            int l = tid + i * 256;
            int c = l & 63, k = l >> 6;
            Bs[cur][k][c] = rb[i];
        }
        __syncthreads();
        if (kt + 1 < nk) {
            int k0 = (kt + 1) * BK;
            #pragma unroll
            for (int i = 0; i < 8; i++) {
                int l = tid + i * 256;
                int k = l & 15, m = l >> 4;
                int gm = bm + m, gk = k0 + k;
                ra[i] = (gm < n && gk < kin) ? A[(size_t)gm * lda + gk] : 0.f;
            }
            #pragma unroll
            for (int i = 0; i < 4; i++) {
                int l = tid + i * 256;
                int c = l & 63, k = l >> 6;
                int gk = k0 + k, gc = bn + c;
                rb[i] = (gk < kin && gc < kout) ? W[(size_t)gk * kout + gc] : 0.f;
            }
        }
        #pragma unroll
        for (int k = 0; k < BK; k++) {
            const float* ar = &As[cur][k][ty * 8];
            float4 a0 = *(const float4*)(ar);
            float4 a1 = *(const float4*)(ar + 4);
            const ull* br = (const ull*)Bs[cur][k];
            ull b0 = br[tx * 2], b1 = br[tx * 2 + 1];
            ull s;
            s = splat2(a0.x); ffma2(acc[0][0], s, b0); ffma2(acc[0][1], s, b1);
            s = splat2(a0.y); ffma2(acc[1][0], s, b0); ffma2(acc[1][1], s, b1);
            s = splat2(a0.z); ffma2(acc[2][0], s, b0); ffma2(acc[2][1], s, b1);
            s = splat2(a0.w); ffma2(acc[3][0], s, b0); ffma2(acc[3][1], s, b1);
            s = splat2(a1.x); ffma2(acc[4][0], s, b0); ffma2(acc[4][1], s, b1);
            s = splat2(a1.y); ffma2(acc[5][0], s, b0); ffma2(acc[5][1], s, b1);
            s = splat2(a1.z); ffma2(acc[6][0], s, b0); ffma2(acc[6][1], s, b1);
            s = splat2(a1.w); ffma2(acc[7][0], s, b0); ffma2(acc[7][1], s, b1);
        }
        __syncthreads();
    }

    #pragma unroll
    for (int i = 0; i < 8; i++) {
        int m = bm + ty * 8 + i;
        if (m >= n) continue;
        #pragma unroll
        for (int j = 0; j < 2; j++) {
            float lo, hi;
            unpack2(acc[i][j], lo, hi);
            int c0 = bn + tx * 4 + 2 * j;
            if (c0 < kout) {
                float v = lo + bias[c0];
                if (relu) v = fmaxf(v, 0.f);
                C[(size_t)m * ldc + c0] = v;
            }
            if (c0 + 1 < kout) {
                float v = hi + bias[c0 + 1];
                if (relu) v = fmaxf(v, 0.f);
                C[(size_t)m * ldc + c0 + 1] = v;
            }
        }
    }
}

// ---------------- gather + max over KNN neighbors ---------------------------
__global__ void gathermax_kernel(const float* __restrict__ Y,
                                 const int* __restrict__ idx,
                                 float* __restrict__ out, int ldo,
                                 float* __restrict__ out2, int n)
{
    int i = blockIdx.x;
    if (i >= n) return;
    int d = threadIdx.x; // 64 threads
    const int* ip = idx + (size_t)i * KNN;
    float m = -FLT_MAX;
    #pragma unroll
    for (int k = 0; k < KNN; k++) {
        int j = ip[k];
        m = fmaxf(m, Y[(size_t)j * 64 + d]);
    }
    out[(size_t)i * ldo + d] = m;
    if (out2) out2[(size_t)i * 64 + d] = m;
}

// ---------------- MaxPool1d(2) over first 192 cols of Z ---------------------
__global__ void maxpool_kernel(const float* __restrict__ Z,
                               float* __restrict__ P, int n)
{
    int t = blockIdx.x * blockDim.x + threadIdx.x;
    if (t >= n * 96) return;
    int i = t / 96, j = t - i * 96;
    const float* r = Z + (size_t)i * 1216 + 2 * j;
    P[t] = fmaxf(r[0], r[1]);
}

// -----------------------------------------------------------------------------
extern "C" void kernel_launch(void* const* d_in, const int* in_sizes, int n_in,
                              void* d_out, int out_size)
{
    const float* X   = (const float*)d_in[0];
    const float* w1  = (const float*)d_in[1];
    const float* b1  = (const float*)d_in[2];
    const float* w2  = (const float*)d_in[3];
    const float* b2  = (const float*)d_in[4];
    const float* w3  = (const float*)d_in[5];
    const float* b3  = (const float*)d_in[6];
    const float* wc1 = (const float*)d_in[7];
    const float* bc1 = (const float*)d_in[8];
    const float* wc2 = (const float*)d_in[9];
    const float* bc2 = (const float*)d_in[10];
    const float* wc3 = (const float*)d_in[11];
    const float* bc3 = (const float*)d_in[12];
    const float* wc4 = (const float*)d_in[13];
    const float* bc4 = (const float*)d_in[14];
    float* out = (float*)d_out;

    int n = in_sizes[0] / 9;
    if (n > NMAX) n = NMAX;

    float *Z, *Y, *Fc, *P, *Z1, *Z2, *Z3, *nrm;
    int* idx;
    __half *hi, *lo;
    cudaGetSymbolAddress((void**)&Z,   g_Z);
    cudaGetSymbolAddress((void**)&Y,   g_Y);
    cudaGetSymbolAddress((void**)&Fc,  g_Fc);
    cudaGetSymbolAddress((void**)&P,   g_P);
    cudaGetSymbolAddress((void**)&Z1,  g_Z1);
    cudaGetSymbolAddress((void**)&Z2,  g_Z2);
    cudaGetSymbolAddress((void**)&Z3,  g_Z3);
    cudaGetSymbolAddress((void**)&nrm, g_norm);
    cudaGetSymbolAddress((void**)&idx, g_idx);
    cudaGetSymbolAddress((void**)&hi,  g_hi);
    cudaGetSymbolAddress((void**)&lo,  g_lo);

    int knnB = n / 128;

    const int SM16 = 1024 + 6 * (128 * 24 * 2) + 128 * 130 * 4;  // 104448
    const int SM64 = 1024 + 6 * (128 * 72 * 2) + 128 * 130 * 4;  // 178176
    cudaFuncSetAttribute(knn_mma_kernel<16>,
                         cudaFuncAttributeMaxDynamicSharedMemorySize, SM16);
    cudaFuncSetAttribute(knn_mma_kernel<64>,
                         cudaFuncAttributeMaxDynamicSharedMemorySize, SM64);

    auto lin = [&](const float* A, int lda, const float* W, const float* bias,
                   float* C, int ldc, int kin, int kout, int relu) {
        dim3 grid((kout + 63) / 64, (n + 127) / 128);
        linear_kernel<<<grid, 256>>>(A, lda, W, bias, C, ldc, n, kin, kout, relu);
    };

    // ---- Block 1: knn(X, D=9); Y1 = X@w1+b1; X1 = max-gather
    lin(X, 9, w1, b1, Y, 64, 9, 64, 0);
    splitnorm_kernel<16, 8><<<(n * 8 + 255) / 256, 256>>>(X, 9, 9, hi, lo, nrm, n);
    knn_mma_kernel<16><<<knnB, 256, SM16>>>(hi, lo, nrm, idx, n);
    gathermax_kernel<<<n, 64>>>(Y, idx, Z + 0, 1216, Fc, n);

    // ---- Block 2: knn(X1, D=64); Y2 = X1@w2+b2
    splitnorm_kernel<64, 32><<<(n * 32 + 255) / 256, 256>>>(Fc, 64, 64, hi, lo, nrm, n);
    lin(Fc, 64, w2, b2, Y, 64, 64, 64, 0);
    knn_mma_kernel<64><<<knnB, 256, SM64>>>(hi, lo, nrm, idx, n);
    gathermax_kernel<<<n, 64>>>(Y, idx, Z + 64, 1216, Fc, n);

    // ---- Block 3: knn(X2, D=64); Y3 = X2@w2+b2
    splitnorm_kernel<64, 32><<<(n * 32 + 255) / 256, 256>>>(Fc, 64, 64, hi, lo, nrm, n);
    knn_mma_kernel<64><<<knnB, 256, SM64>>>(hi, lo, nrm, idx, n);
    lin(Fc, 64, w2, b2, Y, 64, 64, 64, 0);
    gathermax_kernel<<<n, 64>>>(Y, idx, Z + 128, 1216, (float*)0, n);

    // ---- Head: P = maxpool2(Z[:,0:192]); H = P@w3+b3 -> Z[:,192:1216]
    maxpool_kernel<<<(n * 96 + 255) / 256, 256>>>(Z, P, n);
    lin(P, 96, w3, b3, Z + 192, 1216, 96, 1024, 0);

    // ---- Classifier MLP
    lin(Z,  1216, wc1, bc1, Z1, 256, 1216, 256, 1);
    lin(Z1, 256,  wc2, bc2, Z2, 256, 256,  256, 1);
    lin(Z2, 256,  wc3, bc3, Z3, 128, 256,  128, 1);
    lin(Z3, 128,  wc4, bc4, out, 3, 128,   3,  0);
}

// round 17
// speedup vs baseline: 1.7020x; 1.0261x over previous
#include <cuda_runtime.h>
#include <cuda_fp16.h>
#include <math.h>
#include <float.h>
#include <stdint.h>

#define NMAX 16384
#define KNN 20

// ---------------- scratch (device globals; no allocation allowed) ----------
__device__ float g_Z [NMAX * 1216];
__device__ float g_Y [NMAX * 64];
__device__ float g_Fc[NMAX * 64];
__device__ float g_P [NMAX * 96];
__device__ float g_Z1[NMAX * 256];
__device__ float g_Z2[NMAX * 256];
__device__ float g_Z3[NMAX * 128];
__device__ int   g_idx[NMAX * KNN];
__device__ float g_norm[NMAX];
__device__ __half g_hi[NMAX * 64];
__device__ __half g_lo[NMAX * 64];

// ---------------- helpers ----------------------------------------------------
__device__ __forceinline__ uint32_t smem_to_u32(const void* p) {
    uint32_t a;
    asm("{ .reg .u64 t; cvta.to.shared.u64 t, %1; cvt.u32.u64 %0, t; }"
        : "=r"(a) : "l"(p));
    return a;
}
__device__ __forceinline__ void cp_async16(uint32_t dst, const void* src) {
    asm volatile("cp.async.cg.shared.global [%0], [%1], 16;"
                 :: "r"(dst), "l"(src) : "memory");
}
__device__ __forceinline__ void cp_commit() {
    asm volatile("cp.async.commit_group;" ::: "memory");
}
__device__ __forceinline__ void cp_wait0() {
    asm volatile("cp.async.wait_group 0;" ::: "memory");
}
__device__ __forceinline__ void ldsm_x4(uint32_t& r0, uint32_t& r1,
                                        uint32_t& r2, uint32_t& r3, uint32_t a) {
    asm volatile("ldmatrix.sync.aligned.m8n8.x4.shared.b16 {%0,%1,%2,%3}, [%4];"
                 : "=r"(r0), "=r"(r1), "=r"(r2), "=r"(r3) : "r"(a));
}
__device__ __forceinline__ void mma_f16(float& c0, float& c1, float& c2, float& c3,
                                        uint32_t a0, uint32_t a1, uint32_t a2, uint32_t a3,
                                        uint32_t b0, uint32_t b1) {
    asm volatile("mma.sync.aligned.m16n8k16.row.col.f32.f16.f16.f32 "
                 "{%0,%1,%2,%3}, {%4,%5,%6,%7}, {%8,%9}, {%0,%1,%2,%3};"
                 : "+f"(c0), "+f"(c1), "+f"(c2), "+f"(c3)
                 : "r"(a0), "r"(a1), "r"(a2), "r"(a3), "r"(b0), "r"(b1));
}

// ---------------- packed f32x2 helpers --------------------------------------
typedef unsigned long long ull;
__device__ __forceinline__ void ffma2(ull& acc, ull a, ull b) {
    asm("fma.rn.f32x2 %0, %1, %2, %0;" : "+l"(acc) : "l"(a), "l"(b));
}
__device__ __forceinline__ ull splat2(float x) {
    unsigned int u = __float_as_uint(x);
    ull r;
    asm("mov.b64 %0, {%1, %1};" : "=l"(r) : "r"(u));
    return r;
}
__device__ __forceinline__ void unpack2(ull v, float& lo, float& hi) {
    unsigned int a, b;
    asm("mov.b64 {%0, %1}, %2;" : "=r"(a), "=r"(b) : "l"(v));
    lo = __uint_as_float(a); hi = __uint_as_float(b);
}

// ---------------- fused fp32 -> fp16 hi/lo split + row norms -----------------
template<int DB, int TPR>
__global__ void splitnorm_kernel(const float* __restrict__ F, int ld, int D,
                                 __half* __restrict__ hi,
                                 __half* __restrict__ lo,
                                 float* __restrict__ norms, int n)
{
    int t = blockIdx.x * blockDim.x + threadIdx.x;
    int r = t / TPR, g = t - r * TPR;
    if (r >= n) return;
    int c = g * 2;
    float x0 = (c     < D) ? F[(size_t)r * ld + c]     : 0.f;
    float x1 = (c + 1 < D) ? F[(size_t)r * ld + c + 1] : 0.f;
    __half h0 = __float2half_rn(x0), h1 = __float2half_rn(x1);
    hi[(size_t)r * DB + c]     = h0;
    hi[(size_t)r * DB + c + 1] = h1;
    lo[(size_t)r * DB + c]     = __float2half_rn(x0 - __half2float(h0));
    lo[(size_t)r * DB + c + 1] = __float2half_rn(x1 - __half2float(h1));
    float s = x0 * x0 + x1 * x1;
    #pragma unroll
    for (int o = TPR / 2; o > 0; o >>= 1)
        s += __shfl_xor_sync(0xffffffffu, s, o);
    if (g == 0) norms[r] = s;
}

// ---------------- top-k bubble insert ----------------------------------------
__device__ __forceinline__ void topk_insert(float (&bk)[KNN], int (&bi)[KNN],
                                            float kv, int ci)
{
    float vk = kv; int vi = ci;
    #pragma unroll
    for (int p = 0; p < KNN; ++p) {
        bool sw = vk < bk[p];
        float tf = bk[p]; int ti = bi[p];
        if (sw) { bk[p] = vk; bi[p] = vi; vk = tf; vi = ti; }
    }
}

// ---------------- mma.sync kNN top-20, 64 queries/CTA, 2 CTAs/SM -------------
// TQ=64 queries, 128-candidate tiles, single-buffered C so TWO independent
// CTAs co-reside per SM and overlap each other's GEMM/STS/selection/barrier
// phases. 8 warps each m16 x n64; C(t+1) load issues during selection of t.
// Selection: 4 threads/query x 32 candidates + exact 4-list (key, lower
// index) lexicographic merge (= jax.lax.top_k).
// MERGE SCRATCH (R17 fix): keyBuf/idxBuf contiguous at OFF_C (40960 B), which
// fits inside allocated smem for BOTH instantiations (R16 placed idxBuf at
// OFF_C sized 2*CTB, overflowing into S for DB=16 -> corrupt indices -> IMA).
template<int DB>   // fp16 K per term: 16 (D=9) or 64
__global__ __launch_bounds__(256, 2)
void knn_mma_kernel(const __half* __restrict__ Fhi,
                    const __half* __restrict__ Flo,
                    const float* __restrict__ norms,
                    int* __restrict__ out_idx, int n)
{
    constexpr int NSTEP = DB / 16;
    constexpr int CHB = DB / 8;            // 16B chunks per row
    constexpr int SQH = DB + 8;            // smem row stride in halves
    constexpr int QTB = 64  * SQH * 2;     // query tile bytes (64 rows)
    constexpr int CTB = 128 * SQH * 2;     // candidate tile bytes (128 rows)
    constexpr int OFF_QHI = 1024;          // sN[2][128] at 0
    constexpr int OFF_QLO = OFF_QHI + QTB;
    constexpr int OFF_C   = OFF_QLO + QTB;        // single buffer [hi|lo]
    constexpr int OFF_S   = OFF_C + 2 * CTB;      // S[64][130] float

    extern __shared__ char smem[];
    const uint32_t sb = smem_to_u32(smem);
    float* sN = (float*)smem;
    float* S  = (float*)(smem + OFF_S);

    const int tid = threadIdx.x;
    const int warp = tid >> 5, lane = tid & 31;
    const int q0 = blockIdx.x * 64;

    auto load_q = [&](uint32_t dstoff, const __half* src) {
        #pragma unroll
        for (int e = tid; e < 64 * CHB; e += 256) {
            int r = e / CHB, c = e - r * CHB;
            cp_async16(sb + dstoff + (uint32_t)(r * SQH + c * 8) * 2,
                       src + (size_t)r * DB + c * 8);
        }
    };
    auto load_c = [&](const __half* srcHi, const __half* srcLo) {
        #pragma unroll
        for (int e = tid; e < 128 * CHB; e += 256) {
            int r = e / CHB, c = e - r * CHB;
            uint32_t o = (uint32_t)(r * SQH + c * 8) * 2;
            cp_async16(sb + OFF_C + o,       srcHi + (size_t)r * DB + c * 8);
            cp_async16(sb + OFF_C + CTB + o, srcLo + (size_t)r * DB + c * 8);
        }
    };

    // prologue: queries + C(0) + norms(0)
    load_q(OFF_QHI, Fhi + (size_t)q0 * DB);
    load_q(OFF_QLO, Flo + (size_t)q0 * DB);
    load_c(Fhi, Flo);
    if (tid < 32) cp_async16(sb + tid * 16, norms + tid * 4);
    cp_commit();
    cp_wait0();
    __syncthreads();

    // fragment addressing: warp (w&3) -> 16 query rows, (w>>2) -> 64-col half
    const int m0 = (warp & 3) * 16;
    const int ch = warp >> 2;
    const uint32_t aOff = (uint32_t)(((m0 + (lane & 15)) * SQH + (lane >> 4) * 8) * 2);
    const uint32_t aHi = sb + OFF_QHI + aOff;
    const uint32_t aLo = sb + OFF_QLO + aOff;
    const uint32_t bOff = (uint32_t)((((lane & 7) + ((lane >> 4) << 3) + ch * 64) * SQH
                                      + ((lane >> 3) & 1) * 8) * 2);

    float best[KNN]; int bidx[KNN];
    #pragma unroll
    for (int k = 0; k < KNN; k++) { best[k] = 3.0e38f; bidx[k] = 0; }
    float worst = 3.0e38f;

    const int selq = tid & 63, selh = tid >> 6;   // 4 threads per query
    const int T = n >> 7;

    for (int t = 0; t < T; t++) {
        // ---- GEMM: 3-term fp16 split, warp computes m16 x n64 ----
        float acc[8][4];
        #pragma unroll
        for (int f = 0; f < 8; f++)
            #pragma unroll
            for (int j = 0; j < 4; j++) acc[f][j] = 0.f;

        const uint32_t cHi = sb + OFF_C + bOff;
        const uint32_t cLo = cHi + CTB;

        #pragma unroll
        for (int term = 0; term < 3; term++) {
            uint32_t aBase = (term == 2) ? aLo : aHi;
            uint32_t bBase = (term == 1) ? cLo : cHi;
            #pragma unroll
            for (int k = 0; k < NSTEP; k++) {
                uint32_t a0, a1, a2, a3;
                ldsm_x4(a0, a1, a2, a3, aBase + k * 32);
                #pragma unroll
                for (int f = 0; f < 4; f++) {
                    uint32_t b0, b1, b2, b3;
                    ldsm_x4(b0, b1, b2, b3,
                            bBase + k * 32 + (uint32_t)(f * 16 * SQH * 2));
                    mma_f16(acc[2*f][0], acc[2*f][1], acc[2*f][2], acc[2*f][3],
                            a0, a1, a2, a3, b0, b1);
                    mma_f16(acc[2*f+1][0], acc[2*f+1][1], acc[2*f+1][2], acc[2*f+1][3],
                            a0, a1, a2, a3, b2, b3);
                }
            }
        }

        // ---- dot tile -> shared ----
        {
            int r0 = m0 + (lane >> 2);
            int cc = ch * 64 + (lane & 3) * 2;
            #pragma unroll
            for (int f = 0; f < 8; f++) {
                *(float2*)&S[r0 * 130 + cc + f * 8] =
                    make_float2(acc[f][0], acc[f][1]);
                *(float2*)&S[(r0 + 8) * 130 + cc + f * 8] =
                    make_float2(acc[f][2], acc[f][3]);
            }
        }
        __syncthreads();   // S(t) ready; C consumed -> safe to overwrite

        // ---- issue load of C(t+1) (overlaps with selection below) ----
        if (t + 1 < T) {
            int row0 = (t + 1) << 7;
            load_c(Fhi + (size_t)row0 * DB, Flo + (size_t)row0 * DB);
            if (tid < 32)
                cp_async16(sb + ((t + 1) & 1) * 512 + tid * 16,
                           norms + row0 + tid * 4);
        }
        cp_commit();

        // ---- selection: 4 threads/query, 32 candidates each ----
        {
            const float* srow = S + selq * 130 + selh * 32;
            const float* snp  = sN + (t & 1) * 128 + selh * 32;
            int cbaseg = (t << 7) + selh * 32;
            #pragma unroll 4
            for (int j = 0; j < 16; j++) {
                float2 dp = *(const float2*)(srow + 2 * j);
                float2 sn = *(const float2*)(snp + 2 * j);
                float k0 = __fmaf_rn(-2.f, dp.x, sn.x);
                float k1 = __fmaf_rn(-2.f, dp.y, sn.y);
                if (k0 < worst) {
                    topk_insert(best, bidx, k0, cbaseg + 2 * j);
                    worst = best[KNN - 1];
                }
                if (k1 < worst) {
                    topk_insert(best, bidx, k1, cbaseg + 2 * j + 1);
                    worst = best[KNN - 1];
                }
            }
        }
        cp_wait0();
        __syncthreads();   // C(t+1) + norms visible; S free for next STS
    }

    // ---- merge 4 sorted lists per query (exact (key,idx) lexicographic) ----
    // contiguous scratch at OFF_C: keyBuf 64*80*4 B, then idxBuf 64*80*4 B.
    // Fits: DB=16: 7168+40960=48128 <= 52736; DB=64: 19456+40960=60416 <= 89600.
    float* keyBuf = (float*)(smem + OFF_C);
    int*   idxBuf = (int*)(smem + OFF_C + 64 * 80 * 4);
    #pragma unroll
    for (int p = 0; p < KNN; p++) {
        keyBuf[selq * 80 + selh * 20 + p] = best[p];
        idxBuf[selq * 80 + selh * 20 + p] = bidx[p];
    }
    __syncthreads();
    if (tid < 64) {
        const float* kb = keyBuf + tid * 80;
        const int*   ib = idxBuf + tid * 80;
        int p0 = 0, p1 = 0, p2 = 0, p3 = 0;
        int* outp = out_idx + (size_t)(q0 + tid) * KNN;
        #pragma unroll
        for (int o = 0; o < KNN; o++) {
            float k0 = kb[p0],      k1 = kb[20 + p1];
            float k2 = kb[40 + p2], k3 = kb[60 + p3];
            int   i0 = ib[p0],      i1 = ib[20 + p1];
            int   i2 = ib[40 + p2], i3 = ib[60 + p3];
            bool b01 = (k1 < k0) || (k1 == k0 && i1 < i0);
            float ka = b01 ? k1 : k0; int ia = b01 ? i1 : i0;
            bool b23 = (k3 < k2) || (k3 == k2 && i3 < i2);
            float kc = b23 ? k3 : k2; int ic = b23 ? i3 : i2;
            bool bac = (kc < ka) || (kc == ka && ic < ia);
            outp[o] = bac ? ic : ia;
            if (bac) { if (b23) p3++; else p2++; }
            else     { if (b01) p1++; else p0++; }
        }
    }
}

// ---------------- fp32 tiled linear v2: 128x64 tile, 8x4/thread -------------
__global__ __launch_bounds__(256)
void linear_kernel(const float* __restrict__ A, int lda,
                   const float* __restrict__ W,
                   const float* __restrict__ bias,
                   float* __restrict__ C, int ldc,
                   int n, int kin, int kout, int relu)
{
    const int BK = 16;
    __shared__ __align__(16) float As[2][BK][132];
    __shared__ __align__(16) float Bs[2][BK][64];

    int bm = blockIdx.y * 128, bn = blockIdx.x * 64;
    int tid = threadIdx.x;
    int tx = tid & 15, ty = tid >> 4;

    ull acc[8][2];
    #pragma unroll
    for (int i = 0; i < 8; i++) { acc[i][0] = 0ULL; acc[i][1] = 0ULL; }

    float ra[8], rb[4];
    #pragma unroll
    for (int i = 0; i < 8; i++) {
        int l = tid + i * 256;
        int k = l & 15, m = l >> 4;
        int gm = bm + m;
        ra[i] = (gm < n && k < kin) ? A[(size_t)gm * lda + k] : 0.f;
    }
    #pragma unroll
    for (int i = 0; i < 4; i++) {
        int l = tid + i * 256;
        int c = l & 63, k = l >> 6;
        int gc = bn + c;
        rb[i] = (k < kin && gc < kout) ? W[(size_t)k * kout + gc] : 0.f;
    }

    int nk = (kin + BK - 1) / BK;
    for (int kt = 0; kt < nk; kt++) {
        int cur = kt & 1;
        #pragma unroll
        for (int i = 0; i < 8; i++) {
            int l = tid + i * 256;
            int k = l & 15, m = l >> 4;
            As[cur][k][m] = ra[i];
        }
        #pragma unroll
        for (int i = 0; i < 4; i++) {
            int l = tid + i * 256;
            int c = l & 63, k = l >> 6;
            Bs[cur][k][c] = rb[i];
        }
        __syncthreads();
        if (kt + 1 < nk) {
            int k0 = (kt + 1) * BK;
            #pragma unroll
            for (int i = 0; i < 8; i++) {
                int l = tid + i * 256;
                int k = l & 15, m = l >> 4;
                int gm = bm + m, gk = k0 + k;
                ra[i] = (gm < n && gk < kin) ? A[(size_t)gm * lda + gk] : 0.f;
            }
            #pragma unroll
            for (int i = 0; i < 4; i++) {
                int l = tid + i * 256;
                int c = l & 63, k = l >> 6;
                int gk = k0 + k, gc = bn + c;
                rb[i] = (gk < kin && gc < kout) ? W[(size_t)gk * kout + gc] : 0.f;
            }
        }
        #pragma unroll
        for (int k = 0; k < BK; k++) {
            const float* ar = &As[cur][k][ty * 8];
            float4 a0 = *(const float4*)(ar);
            float4 a1 = *(const float4*)(ar + 4);
            const ull* br = (const ull*)Bs[cur][k];
            ull b0 = br[tx * 2], b1 = br[tx * 2 + 1];
            ull s;
            s = splat2(a0.x); ffma2(acc[0][0], s, b0); ffma2(acc[0][1], s, b1);
            s = splat2(a0.y); ffma2(acc[1][0], s, b0); ffma2(acc[1][1], s, b1);
            s = splat2(a0.z); ffma2(acc[2][0], s, b0); ffma2(acc[2][1], s, b1);
            s = splat2(a0.w); ffma2(acc[3][0], s, b0); ffma2(acc[3][1], s, b1);
            s = splat2(a1.x); ffma2(acc[4][0], s, b0); ffma2(acc[4][1], s, b1);
            s = splat2(a1.y); ffma2(acc[5][0], s, b0); ffma2(acc[5][1], s, b1);
            s = splat2(a1.z); ffma2(acc[6][0], s, b0); ffma2(acc[6][1], s, b1);
            s = splat2(a1.w); ffma2(acc[7][0], s, b0); ffma2(acc[7][1], s, b1);
        }
        __syncthreads();
    }

    #pragma unroll
    for (int i = 0; i < 8; i++) {
        int m = bm + ty * 8 + i;
        if (m >= n) continue;
        #pragma unroll
        for (int j = 0; j < 2; j++) {
            float lo, hi;
            unpack2(acc[i][j], lo, hi);
            int c0 = bn + tx * 4 + 2 * j;
            if (c0 < kout) {
                float v = lo + bias[c0];
                if (relu) v = fmaxf(v, 0.f);
                C[(size_t)m * ldc + c0] = v;
            }
            if (c0 + 1 < kout) {
                float v = hi + bias[c0 + 1];
                if (relu) v = fmaxf(v, 0.f);
                C[(size_t)m * ldc + c0 + 1] = v;
            }
        }
    }
}

// ---------------- gather + max over KNN neighbors ---------------------------
__global__ void gathermax_kernel(const float* __restrict__ Y,
                                 const int* __restrict__ idx,
                                 float* __restrict__ out, int ldo,
                                 float* __restrict__ out2, int n)
{
    int i = blockIdx.x;
    if (i >= n) return;
    int d = threadIdx.x; // 64 threads
    const int* ip = idx + (size_t)i * KNN;
    float m = -FLT_MAX;
    #pragma unroll
    for (int k = 0; k < KNN; k++) {
        int j = ip[k];
        m = fmaxf(m, Y[(size_t)j * 64 + d]);
    }
    out[(size_t)i * ldo + d] = m;
    if (out2) out2[(size_t)i * 64 + d] = m;
}

// ---------------- MaxPool1d(2) over first 192 cols of Z ---------------------
__global__ void maxpool_kernel(const float* __restrict__ Z,
                               float* __restrict__ P, int n)
{
    int t = blockIdx.x * blockDim.x + threadIdx.x;
    if (t >= n * 96) return;
    int i = t / 96, j = t - i * 96;
    const float* r = Z + (size_t)i * 1216 + 2 * j;
    P[t] = fmaxf(r[0], r[1]);
}

// -----------------------------------------------------------------------------
extern "C" void kernel_launch(void* const* d_in, const int* in_sizes, int n_in,
                              void* d_out, int out_size)
{
    const float* X   = (const float*)d_in[0];
    const float* w1  = (const float*)d_in[1];
    const float* b1  = (const float*)d_in[2];
    const float* w2  = (const float*)d_in[3];
    const float* b2  = (const float*)d_in[4];
    const float* w3  = (const float*)d_in[5];
    const float* b3  = (const float*)d_in[6];
    const float* wc1 = (const float*)d_in[7];
    const float* bc1 = (const float*)d_in[8];
    const float* wc2 = (const float*)d_in[9];
    const float* bc2 = (const float*)d_in[10];
    const float* wc3 = (const float*)d_in[11];
    const float* bc3 = (const float*)d_in[12];
    const float* wc4 = (const float*)d_in[13];
    const float* bc4 = (const float*)d_in[14];
    float* out = (float*)d_out;

    int n = in_sizes[0] / 9;
    if (n > NMAX) n = NMAX;

    float *Z, *Y, *Fc, *P, *Z1, *Z2, *Z3, *nrm;
    int* idx;
    __half *hi, *lo;
    cudaGetSymbolAddress((void**)&Z,   g_Z);
    cudaGetSymbolAddress((void**)&Y,   g_Y);
    cudaGetSymbolAddress((void**)&Fc,  g_Fc);
    cudaGetSymbolAddress((void**)&P,   g_P);
    cudaGetSymbolAddress((void**)&Z1,  g_Z1);
    cudaGetSymbolAddress((void**)&Z2,  g_Z2);
    cudaGetSymbolAddress((void**)&Z3,  g_Z3);
    cudaGetSymbolAddress((void**)&nrm, g_norm);
    cudaGetSymbolAddress((void**)&idx, g_idx);
    cudaGetSymbolAddress((void**)&hi,  g_hi);
    cudaGetSymbolAddress((void**)&lo,  g_lo);

    int knnB = n / 64;   // 256 CTAs, 2 per SM

    // smem: 1024(sN) + 2*QTB + 2*CTB + S(64*130*4)
    const int SM16 = 1024 + 2 * (64 * 24 * 2) + 2 * (128 * 24 * 2) + 64 * 130 * 4;   //  52736
    const int SM64 = 1024 + 2 * (64 * 72 * 2) + 2 * (128 * 72 * 2) + 64 * 130 * 4;   //  89600
    cudaFuncSetAttribute(knn_mma_kernel<16>,
                         cudaFuncAttributeMaxDynamicSharedMemorySize, SM16);
    cudaFuncSetAttribute(knn_mma_kernel<64>,
                         cudaFuncAttributeMaxDynamicSharedMemorySize, SM64);

    auto lin = [&](const float* A, int lda, const float* W, const float* bias,
                   float* C, int ldc, int kin, int kout, int relu) {
        dim3 grid((kout + 63) / 64, (n + 127) / 128);
        linear_kernel<<<grid, 256>>>(A, lda, W, bias, C, ldc, n, kin, kout, relu);
    };

    // ---- Block 1: knn(X, D=9); Y1 = X@w1+b1; X1 = max-gather
    lin(X, 9, w1, b1, Y, 64, 9, 64, 0);
    splitnorm_kernel<16, 8><<<(n * 8 + 255) / 256, 256>>>(X, 9, 9, hi, lo, nrm, n);
    knn_mma_kernel<16><<<knnB, 256, SM16>>>(hi, lo, nrm, idx, n);
    gathermax_kernel<<<n, 64>>>(Y, idx, Z + 0, 1216, Fc, n);

    // ---- Block 2: knn(X1, D=64); Y2 = X1@w2+b2
    splitnorm_kernel<64, 32><<<(n * 32 + 255) / 256, 256>>>(Fc, 64, 64, hi, lo, nrm, n);
    lin(Fc, 64, w2, b2, Y, 64, 64, 64, 0);
    knn_mma_kernel<64><<<knnB, 256, SM64>>>(hi, lo, nrm, idx, n);
    gathermax_kernel<<<n, 64>>>(Y, idx, Z + 64, 1216, Fc, n);

    // ---- Block 3: knn(X2, D=64); Y3 = X2@w2+b2
    splitnorm_kernel<64, 32><<<(n * 32 + 255) / 256, 256>>>(Fc, 64, 64, hi, lo, nrm, n);
    knn_mma_kernel<64><<<knnB, 256, SM64>>>(hi, lo, nrm, idx, n);
    lin(Fc, 64, w2, b2, Y, 64, 64, 64, 0);
    gathermax_kernel<<<n, 64>>>(Y, idx, Z + 128, 1216, (float*)0, n);

    // ---- Head: P = maxpool2(Z[:,0:192]); H = P@w3+b3 -> Z[:,192:1216]
    maxpool_kernel<<<(n * 96 + 255) / 256, 256>>>(Z, P, n);
    lin(P, 96, w3, b3, Z + 192, 1216, 96, 1024, 0);

    // ---- Classifier MLP
    lin(Z,  1216, wc1, bc1, Z1, 256, 1216, 256, 1);
    lin(Z1, 256,  wc2, bc2, Z2, 256, 256,  256, 1);
    lin(Z2, 256,  wc3, bc3, Z3, 128, 256,  128, 1);
    lin(Z3, 128,  wc4, bc4, out, 3, 128,   3,  0);
}